// round 5
// baseline (speedup 1.0000x reference)
#include <cuda_runtime.h>
#include <cstdint>

#define EMBED   1024
#define HEADS   16
#define HDIM    64
#define BATCH   2
#define SEQ     2048
#define MTOT    (BATCH*SEQ)   // 4096

// Scratch (static __device__ -- no dynamic allocation allowed)
__device__ float g_qkv [(size_t)MTOT * 3 * EMBED];   // [4096, 3072]
__device__ float g_attn[(size_t)MTOT * EMBED];       // [4096, 1024]

// ============================================================================
// helpers
// ============================================================================
__device__ __forceinline__ uint32_t smem_u32(const void* p) {
    uint32_t a;
    asm("{ .reg .u64 t; cvta.to.shared.u64 t, %1; cvt.u32.u64 %0, t; }"
        : "=r"(a) : "l"(p));
    return a;
}
__device__ __forceinline__ float f2tf32(float x) {
    uint32_t u;
    asm("cvt.rna.tf32.f32 %0, %1;" : "=r"(u) : "f"(x));
    return __uint_as_float(u);
}
__device__ __forceinline__ void ldsm_x4(uint32_t* r, uint32_t addr) {
    asm volatile("ldmatrix.sync.aligned.m8n8.x4.shared.b16 {%0,%1,%2,%3}, [%4];"
        : "=r"(r[0]), "=r"(r[1]), "=r"(r[2]), "=r"(r[3]) : "r"(addr));
}
__device__ __forceinline__ void ldsm_x2(uint32_t* r, uint32_t addr) {
    asm volatile("ldmatrix.sync.aligned.m8n8.x2.shared.b16 {%0,%1}, [%2];"
        : "=r"(r[0]), "=r"(r[1]) : "r"(addr));
}
__device__ __forceinline__ void mma_tf32(float* d, const uint32_t* a, const uint32_t* b) {
    asm volatile(
        "mma.sync.aligned.m16n8k8.row.col.f32.tf32.tf32.f32 "
        "{%0,%1,%2,%3}, {%4,%5,%6,%7}, {%8,%9}, {%0,%1,%2,%3};"
        : "+f"(d[0]), "+f"(d[1]), "+f"(d[2]), "+f"(d[3])
        : "r"(a[0]), "r"(a[1]), "r"(a[2]), "r"(a[3]), "r"(b[0]), "r"(b[1]));
}
__device__ __forceinline__ void cp_async16(uint32_t dst, const void* src) {
    asm volatile("cp.async.cg.shared.global [%0], [%1], 16;"
                 :: "r"(dst), "l"(src) : "memory");
}
#define CP_COMMIT() asm volatile("cp.async.commit_group;" ::: "memory")
#define CP_WAIT1()  asm volatile("cp.async.wait_group 1;" ::: "memory")
#define CP_WAIT0()  asm volatile("cp.async.wait_group 0;" ::: "memory")

// ============================================================================
// tf32 tensor-core GEMM (NT): C[M,N] = A[M,K] @ B[N,K]^T + bias[N]
// CTA 128x128, BK=32 floats. NOW: 2-stage smem pipeline, ONE sync per iter:
//   sync -> issue LDG(kt+1) -> compute stage[kt&1] -> convert+STS stage[(kt+1)&1]
// ============================================================================
#define BKF 32
#define G_STAGE 32768            // sA 16KB + sB 16KB per stage
#define GEMM_DSMEM (2 * G_STAGE + 1024)

__global__ __launch_bounds__(256, 1)
void gemm_tf32_mma(const float* __restrict__ A,
                   const float* __restrict__ B,
                   const float* __restrict__ bias,
                   float* __restrict__ C,
                   int M, int N, int K)
{
    extern __shared__ char gsm[];
    const uint32_t raw  = smem_u32(gsm);
    const uint32_t base = (raw + 1023u) & ~1023u;
    char* pb = gsm + (base - raw);

    const int tid  = threadIdx.x;
    const int wid  = tid >> 5;
    const int lane = tid & 31;
    const int m0   = blockIdx.y * 128;
    const int n0   = blockIdx.x * 128;
    const int wm   = (wid & 1) * 64;
    const int wn   = (wid >> 1) * 32;

    // loader mapping: row = tid>>1 (0..127), half = tid&1 -> 16 floats
    const int lrow  = tid >> 1;
    const int lhalf = tid & 1;
    const float* Arow = A + (size_t)(m0 + lrow) * K + lhalf * 16;
    const float* Brow = B + (size_t)(n0 + lrow) * K + lhalf * 16;
    uint32_t st_off[4];
#pragma unroll
    for (int q = 0; q < 4; q++) {
        uint32_t bo = (uint32_t)lrow * 128u + (uint32_t)lhalf * 64u + q * 16u;
        st_off[q] = bo ^ ((bo >> 3) & 0x70);
    }

    // ldmatrix addressing
    const int aseg  = lane >> 3;
    const int arow  = wm + ((aseg & 1) << 3) + (lane & 7);
    const uint32_t akb = (uint32_t)((aseg >> 1) << 4);
    const int bseg  = (lane >> 3) & 1;
    const int brow  = wn + (lane & 7);
    const uint32_t bkb = (uint32_t)(bseg << 4);
    const uint32_t swmask = (uint32_t)((lane & 7) << 4);
    const uint32_t aRowByte = (uint32_t)arow * 128u;
    const uint32_t bRowByte = (uint32_t)brow * 128u;

    float acc[4][4][4];
#pragma unroll
    for (int i = 0; i < 4; i++)
#pragma unroll
        for (int j = 0; j < 4; j++)
#pragma unroll
            for (int r = 0; r < 4; r++) acc[i][j][r] = 0.f;

    const int KCH = K / BKF;
    float4 av[4], bv[4];

    // prologue: load + convert + store tile 0 into stage 0
#pragma unroll
    for (int q = 0; q < 4; q++) {
        av[q] = *(const float4*)(Arow + q * 4);
        bv[q] = *(const float4*)(Brow + q * 4);
    }
#pragma unroll
    for (int q = 0; q < 4; q++) {
        float4 t;
        t.x = f2tf32(av[q].x); t.y = f2tf32(av[q].y);
        t.z = f2tf32(av[q].z); t.w = f2tf32(av[q].w);
        *(float4*)(pb + st_off[q]) = t;
        t.x = f2tf32(bv[q].x); t.y = f2tf32(bv[q].y);
        t.z = f2tf32(bv[q].z); t.w = f2tf32(bv[q].w);
        *(float4*)(pb + 16384 + st_off[q]) = t;
    }

    for (int kt = 0; kt < KCH; kt++) {
        __syncthreads();   // stage[kt&1] visible; stage[(kt+1)&1] free

        // issue global loads for kt+1 (latency covered by mma below)
        if (kt + 1 < KCH) {
            const float* a = Arow + (size_t)(kt + 1) * BKF;
            const float* b = Brow + (size_t)(kt + 1) * BKF;
#pragma unroll
            for (int q = 0; q < 4; q++) {
                av[q] = *(const float4*)(a + q * 4);
                bv[q] = *(const float4*)(b + q * 4);
            }
        }

        // compute on stage kt&1
        const uint32_t sAa = base + (uint32_t)(kt & 1) * G_STAGE;
        const uint32_t sBa = sAa + 16384u;
#pragma unroll
        for (int ks = 0; ks < 4; ks++) {
            const uint32_t kcolA = ((uint32_t)(ks * 32) + akb) ^ swmask;
            const uint32_t kcolB = ((uint32_t)(ks * 32) + bkb) ^ swmask;
            uint32_t afr[4][4], bfr[4][2];
#pragma unroll
            for (int mt = 0; mt < 4; mt++)
                ldsm_x4(afr[mt], sAa + aRowByte + (uint32_t)(mt * 16 * 128) + kcolA);
#pragma unroll
            for (int nt = 0; nt < 4; nt++)
                ldsm_x2(bfr[nt], sBa + bRowByte + (uint32_t)(nt * 8 * 128) + kcolB);
#pragma unroll
            for (int mt = 0; mt < 4; mt++)
#pragma unroll
                for (int nt = 0; nt < 4; nt++)
                    mma_tf32(acc[mt][nt], afr[mt], bfr[nt]);
        }

        // convert + store tile kt+1 into the other stage
        if (kt + 1 < KCH) {
            char* dst = pb + ((kt + 1) & 1) * G_STAGE;
#pragma unroll
            for (int q = 0; q < 4; q++) {
                float4 t;
                t.x = f2tf32(av[q].x); t.y = f2tf32(av[q].y);
                t.z = f2tf32(av[q].z); t.w = f2tf32(av[q].w);
                *(float4*)(dst + st_off[q]) = t;
                t.x = f2tf32(bv[q].x); t.y = f2tf32(bv[q].y);
                t.z = f2tf32(bv[q].z); t.w = f2tf32(bv[q].w);
                *(float4*)(dst + 16384 + st_off[q]) = t;
            }
        }
    }

    const int rbase = m0 + wm + (lane >> 2);
    const int cbase = n0 + wn + (lane & 3) * 2;
#pragma unroll
    for (int mt = 0; mt < 4; mt++) {
        const int r0 = rbase + mt * 16;
#pragma unroll
        for (int nt = 0; nt < 4; nt++) {
            const int c = cbase + nt * 8;
            const float b0 = __ldg(bias + c);
            const float b1 = __ldg(bias + c + 1);
            float2 v0, v1;
            v0.x = acc[mt][nt][0] + b0; v0.y = acc[mt][nt][1] + b1;
            v1.x = acc[mt][nt][2] + b0; v1.y = acc[mt][nt][3] + b1;
            *(float2*)&C[(size_t)r0 * N + c]       = v0;
            *(float2*)&C[(size_t)(r0 + 8) * N + c] = v1;
        }
    }
}

// ============================================================================
// Tensor-core flash attention (tf32 mma) with cp.async K/V staging pipeline.
// CTA: 128 q-rows of one (b,h). 8 warps, 16 q-rows/warp. Key tile 64.
// Raw fp32 K/V stream one tile ahead into 2-stage staging buffers; the
// convert pass (LDS -> tf32 -> swizzled STS) replaces the exposed LDG.
// ============================================================================
#define BQ  128
#define BKV 64

// dynamic smem layout (bytes from 1024-aligned base):
//  sQ    [128][64]f tf32 sw : 0      .. 32768
//  sK    [ 64][64]f tf32 sw : 32768  .. 49152
//  sVT   [ 64][64]f tf32 sw : 49152  .. 65536
//  sP    [128][64]f tf32 sw : 65536  .. 98304
//  stgK  2 x [64][64]f raw  : 98304  .. 131072
//  stgV  2 x [64][64]f raw  : 131072 .. 163840
//  sM    [64]i              : 163840 .. 164096
#define FA_STG_K  98304
#define FA_STG_V  131072
#define FA_SMEM   (164096 + 1024)

__device__ __forceinline__ uint32_t sw256(int row, int chunk) {
    return (uint32_t)row * 256u + (uint32_t)((chunk ^ (row & 7)) << 4);
}

__global__ __launch_bounds__(256, 1)
void flash_attn_tc(const float* __restrict__ qkv,
                   const int*   __restrict__ mask,
                   float*       __restrict__ out)
{
    extern __shared__ char fsm[];
    const uint32_t raw  = smem_u32(fsm);
    const uint32_t base = (raw + 1023u) & ~1023u;
    char* pb = fsm + (base - raw);
    char* sQ  = pb;
    char* sK  = pb + 32768;
    char* sVT = pb + 49152;
    char* sP  = pb + 65536;
    int*  sM  = (int*)(pb + 163840);
    const uint32_t aQ  = base;
    const uint32_t aK  = base + 32768;
    const uint32_t aVT = base + 49152;
    const uint32_t aP  = base + 65536;

    const int tid  = threadIdx.x;
    const int wid  = tid >> 5;
    const int lane = tid & 31;
    const int qb   = blockIdx.x;
    const int h    = blockIdx.y;
    const int b    = blockIdx.z;

    const size_t rs = 3 * EMBED;
    const float* qg = qkv + (size_t)(b * SEQ) * rs + h * HDIM;
    const float* kg = qg + EMBED;
    const float* vg = qg + 2 * EMBED;
    const int*   mg = mask + b * SEQ;

    // staging copy mapping: row = tid>>2 (0..63), 4 x 16B chunks at (tid&3)*4
    const int srow = tid >> 2;
    const int sch  = (tid & 3) * 4;          // first 16B chunk index (of 16)
    const uint32_t stgK_off = (uint32_t)srow * 256u + (uint32_t)sch * 16u;
    const uint32_t stgV_off = stgK_off;

    // ---- prologue: cp.async tile 0 into stage 0 + mask prefetch
    {
        const float* srck = kg + (size_t)srow * rs + sch * 4;
        const float* srcv = vg + (size_t)srow * rs + sch * 4;
#pragma unroll
        for (int q = 0; q < 4; q++) {
            cp_async16(base + FA_STG_K + stgK_off + q * 16u, srck + q * 4);
            cp_async16(base + FA_STG_V + stgV_off + q * 16u, srcv + q * 4);
        }
        CP_COMMIT();
    }
    int mnext = 0;
    if (tid < BKV) mnext = mg[tid];

    // ---- load Q tile [128][64], tf32-rounded, swizzled
    {
        const int r  = tid >> 1;
        const int cb = (tid & 1) * 8;
        const float* src = qg + (size_t)(qb * BQ + r) * rs;
#pragma unroll
        for (int q = 0; q < 8; q++) {
            const int c = cb + q;
            float4 v = *(const float4*)(src + c * 4);
            v.x = f2tf32(v.x); v.y = f2tf32(v.y);
            v.z = f2tf32(v.z); v.w = f2tf32(v.w);
            *(float4*)(sQ + sw256(r, c)) = v;
        }
    }
    __syncthreads();

    // ---- hoist Q fragments for all 8 k-steps
    const int arow = wid * 16 + ((lane >> 3) & 1) * 8 + (lane & 7);
    const int ach  = lane >> 4;
    uint32_t qf[8][4];
#pragma unroll
    for (int ks = 0; ks < 8; ks++)
        ldsm_x4(qf[ks], aQ + sw256(arow, ks * 2 + ach));

    const int bln = lane & 7;
    const int bch = (lane >> 3) & 1;

    float m_i[2] = {-1e30f, -1e30f};
    float l_i[2] = {0.f, 0.f};
    float oacc[8][4];
#pragma unroll
    for (int j = 0; j < 8; j++)
#pragma unroll
        for (int r = 0; r < 4; r++) oacc[j][r] = 0.f;

    const int NT = SEQ / BKV;
    for (int kt = 0; kt < NT; kt++) {
        const int s  = kt & 1;
        // issue cp.async for tile kt+1 + mask prefetch
        const int mcur = mnext;
        if (kt + 1 < NT) {
            const int sn = (kt + 1) & 1;
            const float* srck = kg + (size_t)((kt + 1) * BKV + srow) * rs + sch * 4;
            const float* srcv = vg + (size_t)((kt + 1) * BKV + srow) * rs + sch * 4;
#pragma unroll
            for (int q = 0; q < 4; q++) {
                cp_async16(base + FA_STG_K + sn * 16384u + stgK_off + q * 16u, srck + q * 4);
                cp_async16(base + FA_STG_V + sn * 16384u + stgV_off + q * 16u, srcv + q * 4);
            }
            CP_COMMIT();
            if (tid < BKV) mnext = mg[(kt + 1) * BKV + tid];
            CP_WAIT1();
        } else {
            CP_WAIT0();
        }
        __syncthreads();   // staged tile kt visible everywhere; PV of kt-1 done

        // ---- convert staged K -> sK (tf32, swizzled); each thread its own chunks
        {
            const char* src = pb + FA_STG_K + s * 16384 + stgK_off;
#pragma unroll
            for (int q = 0; q < 4; q++) {
                float4 v = *(const float4*)(src + q * 16);
                v.x = f2tf32(v.x); v.y = f2tf32(v.y);
                v.z = f2tf32(v.z); v.w = f2tf32(v.w);
                *(float4*)(sK + sw256(srow, sch + q)) = v;
            }
        }
        // ---- convert staged V -> sVT (transpose)
        {
            const char* src = pb + FA_STG_V + s * 16384 + stgV_off;
            const int key = srow;
            const int db  = sch * 4;           // first d of our 16 floats
            const int kc  = key >> 2;
            const int kb  = (key & 3) * 4;
#pragma unroll
            for (int q = 0; q < 4; q++) {
                float4 v = *(const float4*)(src + q * 16);
                const int d0 = db + q * 4;
                *(float*)(sVT + sw256(d0 + 0, kc) + kb) = f2tf32(v.x);
                *(float*)(sVT + sw256(d0 + 1, kc) + kb) = f2tf32(v.y);
                *(float*)(sVT + sw256(d0 + 2, kc) + kb) = f2tf32(v.z);
                *(float*)(sVT + sw256(d0 + 3, kc) + kb) = f2tf32(v.w);
            }
        }
        if (tid < BKV) sM[tid] = mcur;
        __syncthreads();

        // ---- S = Q K^T
        float sacc[8][4];
#pragma unroll
        for (int j = 0; j < 8; j++)
#pragma unroll
            for (int r = 0; r < 4; r++) sacc[j][r] = 0.f;
#pragma unroll
        for (int ks = 0; ks < 8; ks++) {
            uint32_t bfr[8][2];
#pragma unroll
            for (int nf = 0; nf < 8; nf++)
                ldsm_x2(bfr[nf], aK + sw256(nf * 8 + bln, ks * 2 + bch));
#pragma unroll
            for (int nf = 0; nf < 8; nf++)
                mma_tf32(sacc[nf], qf[ks], bfr[nf]);
        }

        // ---- fragment softmax
        float rmax0 = -1e30f, rmax1 = -1e30f;
#pragma unroll
        for (int j = 0; j < 8; j++) {
            const int c = j * 8 + (lane & 3) * 2;
            const int mk0 = sM[c], mk1 = sM[c + 1];
            sacc[j][0] = mk0 ? sacc[j][0] * 0.125f : -1e30f;
            sacc[j][1] = mk1 ? sacc[j][1] * 0.125f : -1e30f;
            sacc[j][2] = mk0 ? sacc[j][2] * 0.125f : -1e30f;
            sacc[j][3] = mk1 ? sacc[j][3] * 0.125f : -1e30f;
            rmax0 = fmaxf(rmax0, fmaxf(sacc[j][0], sacc[j][1]));
            rmax1 = fmaxf(rmax1, fmaxf(sacc[j][2], sacc[j][3]));
        }
        rmax0 = fmaxf(rmax0, __shfl_xor_sync(0xffffffffu, rmax0, 1));
        rmax0 = fmaxf(rmax0, __shfl_xor_sync(0xffffffffu, rmax0, 2));
        rmax1 = fmaxf(rmax1, __shfl_xor_sync(0xffffffffu, rmax1, 1));
        rmax1 = fmaxf(rmax1, __shfl_xor_sync(0xffffffffu, rmax1, 2));

        const float mn0 = fmaxf(m_i[0], rmax0);
        const float mn1 = fmaxf(m_i[1], rmax1);
        const float cr0 = __expf(m_i[0] - mn0);
        const float cr1 = __expf(m_i[1] - mn1);
        m_i[0] = mn0; m_i[1] = mn1;

        float rsum0 = 0.f, rsum1 = 0.f;
#pragma unroll
        for (int j = 0; j < 8; j++) {
            sacc[j][0] = __expf(sacc[j][0] - mn0);
            sacc[j][1] = __expf(sacc[j][1] - mn0);
            sacc[j][2] = __expf(sacc[j][2] - mn1);
            sacc[j][3] = __expf(sacc[j][3] - mn1);
            rsum0 += sacc[j][0] + sacc[j][1];
            rsum1 += sacc[j][2] + sacc[j][3];
        }
        rsum0 += __shfl_xor_sync(0xffffffffu, rsum0, 1);
        rsum0 += __shfl_xor_sync(0xffffffffu, rsum0, 2);
        rsum1 += __shfl_xor_sync(0xffffffffu, rsum1, 1);
        rsum1 += __shfl_xor_sync(0xffffffffu, rsum1, 2);
        l_i[0] = l_i[0] * cr0 + rsum0;
        l_i[1] = l_i[1] * cr1 + rsum1;

#pragma unroll
        for (int j = 0; j < 8; j++) {
            oacc[j][0] *= cr0; oacc[j][1] *= cr0;
            oacc[j][2] *= cr1; oacc[j][3] *= cr1;
        }

        // ---- store P (tf32) for PV mma; rows warp-local
        {
            const int r0 = wid * 16 + (lane >> 2);
#pragma unroll
            for (int j = 0; j < 8; j++) {
                const int c = j * 8 + (lane & 3) * 2;
                const int ch = c >> 2;
                const int cb = (c & 3) * 4;
                float2 v0, v1;
                v0.x = f2tf32(sacc[j][0]); v0.y = f2tf32(sacc[j][1]);
                v1.x = f2tf32(sacc[j][2]); v1.y = f2tf32(sacc[j][3]);
                *(float2*)(sP + sw256(r0,     ch) + cb) = v0;
                *(float2*)(sP + sw256(r0 + 8, ch) + cb) = v1;
            }
        }
        __syncwarp();

        // ---- O += P V^T
#pragma unroll
        for (int ks = 0; ks < 8; ks++) {
            uint32_t af[4];
            ldsm_x4(af, aP + sw256(arow, ks * 2 + ach));
            uint32_t bfr[8][2];
#pragma unroll
            for (int nf = 0; nf < 8; nf++)
                ldsm_x2(bfr[nf], aVT + sw256(nf * 8 + bln, ks * 2 + bch));
#pragma unroll
            for (int nf = 0; nf < 8; nf++)
                mma_tf32(oacc[nf], af, bfr[nf]);
        }
    }

    // ---- epilogue
    const float inv0 = 1.0f / l_i[0];
    const float inv1 = 1.0f / l_i[1];
    const int r0 = qb * BQ + wid * 16 + (lane >> 2);
    const int c0 = h * HDIM + (lane & 3) * 2;
#pragma unroll
    for (int j = 0; j < 8; j++) {
        const int c = c0 + j * 8;
        float2 v0, v1;
        v0.x = oacc[j][0] * inv0; v0.y = oacc[j][1] * inv0;
        v1.x = oacc[j][2] * inv1; v1.y = oacc[j][3] * inv1;
        *(float2*)&out[(size_t)(b * SEQ + r0)     * EMBED + c] = v0;
        *(float2*)&out[(size_t)(b * SEQ + r0 + 8) * EMBED + c] = v1;
    }
}

// ---------------------------------------------------------------------------
extern "C" void kernel_launch(void* const* d_in, const int* in_sizes, int n_in,
                              void* d_out, int out_size)
{
    const float* x    = (const float*)d_in[0];
    const int*   mask = (const int*)  d_in[1];
    const float* Wqkv = (const float*)d_in[2];
    const float* bqkv = (const float*)d_in[3];
    const float* Wout = (const float*)d_in[4];
    const float* bout = (const float*)d_in[5];
    float* out = (float*)d_out;

    float *qkv = nullptr, *attn = nullptr;
    cudaGetSymbolAddress((void**)&qkv,  g_qkv);
    cudaGetSymbolAddress((void**)&attn, g_attn);

    cudaFuncSetAttribute(gemm_tf32_mma,
                         cudaFuncAttributeMaxDynamicSharedMemorySize, GEMM_DSMEM);
    cudaFuncSetAttribute(flash_attn_tc,
                         cudaFuncAttributeMaxDynamicSharedMemorySize, FA_SMEM);

    // 1) qkv = x @ Wqkv^T + bqkv       [4096, 3072]
    {
        dim3 grid((3 * EMBED) / 128, MTOT / 128);
        gemm_tf32_mma<<<grid, 256, GEMM_DSMEM>>>(x, Wqkv, bqkv, qkv,
                                                 MTOT, 3 * EMBED, EMBED);
    }
    // 2) flash attention -> attn       [4096, 1024]
    {
        dim3 grid(SEQ / BQ, HEADS, BATCH);
        flash_attn_tc<<<grid, 256, FA_SMEM>>>(qkv, mask, attn);
    }
    // 3) out = attn @ Wout^T + bout    [4096, 1024]
    {
        dim3 grid(EMBED / 128, MTOT / 128);
        gemm_tf32_mma<<<grid, 256, GEMM_DSMEM>>>(attn, Wout, bout, out,
                                                 MTOT, EMBED, EMBED);
    }
}